// round 15
// baseline (speedup 1.0000x reference)
#include <cuda_runtime.h>
#include <cuda_fp16.h>
#include <stdint.h>
#include <math.h>

#define DF 256
#define NE 8
#define TM 64
#define NT 256
#define MAXB 32768

// ---- smem layout (bytes) ----
#define OFF_PERM 0
#define OFF_B1   1024
#define OFF_B2   2048
#define OFF_C1   3072
#define OFF_A0   4096
#define ASTRIDE  528                        // 256 halfs + pad (conflict-free LDSM)
#define ABUF     (64*ASTRIDE)               // 33792
#define OFF_A1   (OFF_A0 + ABUF)
#define SMEM_BYTES (OFF_A1 + ABUF)          // 71680 -> 2 CTAs/SM

// ---------------- device scratch (zero-initialized at load) --------------------
// g_cursor starts zero (static init); reset ONLY by k_moe's tail after each run.
__device__ int g_cursor[NE];
__device__ int g_done;
__device__ int g_perm[NE * MAXB];
// weights in mma-B fragment layout: [mat][e][kc][wid][j][lane] -> uint4
// linear idx = e*8192 + kc*1024 + wid*128 + j*32 + lane
__device__ __align__(16) uint4 g_wf[2][NE * 8 * 8 * 4 * 32];

__device__ __forceinline__ int expert_of(float t) {
    int e = (int)(t * 8.0f);
    if (e > NE - 1) e = NE - 1;
    if (e < 0) e = 0;
    return e;
}

// ---- merged prep: blocks [0,512) build fragment weights; rest scatter ----------
__global__ void k_prep(const float* __restrict__ W1, const float* __restrict__ W2,
                       const float* __restrict__ t, int B) {
    if (blockIdx.x < 512) {
        int i = blockIdx.x * 256 + threadIdx.x;   // 0..131071
        int mat = i >> 16;
        int u   = i & 65535;
        int tt = u & 31, j = (u >> 5) & 3, wd = (u >> 7) & 7;
        int kc = (u >> 10) & 7, e = u >> 13;
        int n  = wd * 32 + j * 8 + (tt >> 2);
        int k0 = kc * 32 + (tt & 3) * 2;
        const float* W = (mat ? W2 : W1) + (size_t)e * DF * DF + (size_t)n * DF + k0;
        uint4 o;
        __half2 h;
        h = __floats2half2_rn(W[0],  W[1]);  o.x = *(uint32_t*)&h;
        h = __floats2half2_rn(W[8],  W[9]);  o.y = *(uint32_t*)&h;
        h = __floats2half2_rn(W[16], W[17]); o.z = *(uint32_t*)&h;
        h = __floats2half2_rn(W[24], W[25]); o.w = *(uint32_t*)&h;
        g_wf[mat][u] = o;
    } else {
        __shared__ int h[NE], bb[NE];
        if (threadIdx.x < NE) h[threadIdx.x] = 0;
        __syncthreads();
        int i = (blockIdx.x - 512) * blockDim.x + threadIdx.x;
        int e = 0, r = 0;
        bool valid = (i < B);
        if (valid) { e = expert_of(t[i]); r = atomicAdd(&h[e], 1); }
        __syncthreads();
        if (threadIdx.x < NE && h[threadIdx.x])
            bb[threadIdx.x] = atomicAdd(&g_cursor[threadIdx.x], h[threadIdx.x]);
        __syncthreads();
        if (valid) g_perm[e * MAXB + bb[e] + r] = i;
    }
}

// ---------------- helpers ----------------------------------------------------------
__device__ __forceinline__ float sigmf(float x) { return 1.0f / (1.0f + expf(-x)); }
__device__ __forceinline__ float tanh_approx(float x) {
    float r;
    asm("tanh.approx.f32 %0, %1;" : "=f"(r) : "f"(x));
    return r;
}

__device__ __forceinline__ void ldsm4(uint32_t* r, uint32_t addr) {
    asm volatile("ldmatrix.sync.aligned.m8n8.x4.shared.b16 {%0,%1,%2,%3}, [%4];"
        : "=r"(r[0]), "=r"(r[1]), "=r"(r[2]), "=r"(r[3]) : "r"(addr));
}
__device__ __forceinline__ void mma_f16(float* d, const uint32_t* a, uint32_t b0, uint32_t b1) {
    asm volatile("mma.sync.aligned.m16n8k16.row.col.f32.f16.f16.f32 "
        "{%0,%1,%2,%3}, {%4,%5,%6,%7}, {%8,%9}, {%0,%1,%2,%3};"
        : "+f"(d[0]), "+f"(d[1]), "+f"(d[2]), "+f"(d[3])
        : "r"(a[0]), "r"(a[1]), "r"(a[2]), "r"(a[3]), "r"(b0), "r"(b1));
}

__device__ __forceinline__ void sts_f16x4(uint32_t addr, float4 d) {
    __half2 p0 = __floats2half2_rn(d.x, d.y);
    __half2 p1 = __floats2half2_rn(d.z, d.w);
    uint32_t u0 = *reinterpret_cast<uint32_t*>(&p0);
    uint32_t u1 = *reinterpret_cast<uint32_t*>(&p1);
    asm volatile("st.shared.v2.b32 [%0], {%1,%2};" :: "r"(addr), "r"(u0), "r"(u1) : "memory");
}

// GEMM: warp tile 64(M) x 32(N), A from smem buffer aBuf, B frags via LDG.128
// from fragment-ordered global (prefetch one chunk ahead). Warp-rotated k-order
// (rotation = warp id) de-synchronizes LDSM/LDG bursts across warps; FP add
// order per-warp changes but accumulation is exact-workload-identical in spirit.
// If GATHER: streams subtile-1 y rows (2 float4/thread/chunk) into A1.
template<bool GATHER>
__device__ __forceinline__ void gemm256(uint32_t aBuf, const uint4* __restrict__ Wf,
                                        float (&acc)[4][4][4], int lane, int w,
                                        const float* yg0, const float* yg1, uint32_t aSts1) {
    uint32_t aBase = aBuf
        + (uint32_t)(((lane >> 3) & 1) * 8 + (lane & 7)) * ASTRIDE
        + (uint32_t)(lane >> 4) * 16;
    const int rot = w;

    uint4 Bv[4];
#pragma unroll
    for (int j = 0; j < 4; j++) Bv[j] = Wf[rot * 1024 + j * 32];   // chunk `rot`

#pragma unroll
    for (int kc = 0; kc < 8; kc++) {
        int kk  = (kc + rot) & 7;
        int kkn = (kk + 1) & 7;
        float4 v0, v1;
        if (GATHER) {
            v0 = *(const float4*)(yg0 + kc * 32);
            v1 = *(const float4*)(yg1 + kc * 32);
        }
        uint32_t aAddr = aBase + (uint32_t)kk * 64;
        uint32_t a[32];
#pragma unroll
        for (int mt = 0; mt < 4; mt++) {
            ldsm4(a + mt * 8,     aAddr + (uint32_t)(mt * 16) * ASTRIDE);        // ks0
            ldsm4(a + mt * 8 + 4, aAddr + (uint32_t)(mt * 16) * ASTRIDE + 32);   // ks1
        }
#pragma unroll
        for (int j = 0; j < 4; j++) {
            uint4 b = Bv[j];
            if (kc < 7) Bv[j] = Wf[kkn * 1024 + j * 32];   // prefetch next chunk
#pragma unroll
            for (int mt = 0; mt < 4; mt++) {
                mma_f16(acc[mt][j], a + mt * 8,     b.x, b.y);
                mma_f16(acc[mt][j], a + mt * 8 + 4, b.z, b.w);
            }
        }
        if (GATHER) {
            sts_f16x4(aSts1 + (uint32_t)kc * 64, v0);
            sts_f16x4(aSts1 + 32 * ASTRIDE + (uint32_t)kc * 64, v1);
        }
    }
}

// ---------------- main fused MoE kernel --------------------------------------------
// Each CTA processes TWO consecutive 64-row tiles of the SAME expert with a
// double-buffered A: subtile-1's gather is streamed into A1 during GEMM1(s0),
// removing the second serial gather phase and two barriers.
__global__ __launch_bounds__(NT, 2) void k_moe(
    const float* __restrict__ y,
    const float* __restrict__ b1, const float* __restrict__ b2,
    const float* __restrict__ scales,
    const float* __restrict__ shifta, const float* __restrict__ shiftb,
    float* __restrict__ out, int nGrid)
{
    extern __shared__ char smem[];
    const int tid  = threadIdx.x;
    const int lane = tid & 31;
    const int w    = tid >> 5;    // 8 warps along N (32 cols each)

    // ---- block -> (expert, tile-pair) -----------------------------------------
    int bid = blockIdx.x, e = 0, local = -1, acc_t = 0, cnt_e = 0;
#pragma unroll
    for (int q = 0; q < NE; q++) {
        int c  = g_cursor[q];
        int nt = (c + TM - 1) / TM;
        int np = (nt + 1) >> 1;
        if (local < 0 && bid < acc_t + np) { e = q; local = bid - acc_t; cnt_e = c; }
        acc_t += np;
    }

    if (local >= 0) {
        uint32_t su;
        asm("{ .reg .u64 t; cvta.to.shared.u64 t, %1; cvt.u32.u64 %0, t; }" : "=r"(su) : "l"(smem));

        int*   sPerm = (int*)(smem + OFF_PERM);   // 128 rows (both subtiles)
        float* sB1   = (float*)(smem + OFF_B1);
        float* sB2   = (float*)(smem + OFF_B2);
        float* sC1   = (float*)(smem + OFF_C1);

        int base0 = local * 2 * TM;
        int rows0 = cnt_e - base0;          if (rows0 > TM) rows0 = TM;
        int rows1 = cnt_e - base0 - TM;     if (rows1 > TM) rows1 = TM;

        float sa = sigmf(shifta[0]);
        float sb = sigmf(shiftb[0]);
        float cy = 0.5f * (sb - sa);
        sB1[tid] = b1[e * DF + tid];
        sB2[tid] = b2[e * DF + tid];
        sC1[tid] = 0.5f * (sb + sa) * sigmf(scales[tid]);
        // both subtiles' perms (clamped: safe rows for missing tail)
        {
            int gi = base0 + tid;
            if (gi > cnt_e - 1) gi = cnt_e - 1;
            if (tid < 128) sPerm[tid] = g_perm[e * MAXB + gi];
        }
        __syncthreads();

        const uint4* Wf1 = g_wf[0] + e * 8192 + w * 128 + lane;
        const uint4* Wf2 = g_wf[1] + e * 8192 + w * 128 + lane;
        bool need_y = (cy != 0.0f);

        int rb = tid >> 3, q = tid & 7;
        // ---- gather A0 (subtile 0) ---------------------------------------------
        {
            const float* y0 = y + (size_t)sPerm[rb] * DF + q * 4;
            const float* y1 = y + (size_t)sPerm[rb + 32] * DF + q * 4;
            uint32_t d0 = su + OFF_A0 + (uint32_t)rb * ASTRIDE + (uint32_t)q * 8;
            uint32_t d1 = d0 + 32 * ASTRIDE;
#pragma unroll
            for (int c = 0; c < 8; c++) {
                float4 v0 = *(const float4*)(y0 + c * 32);
                float4 v1 = *(const float4*)(y1 + c * 32);
                sts_f16x4(d0 + c * 64, v0);
                sts_f16x4(d1 + c * 64, v1);
            }
        }
        // subtile-1 gather pointers (perm visible since pre-gather barrier)
        const float* yg0 = y + (size_t)sPerm[64 + rb] * DF + q * 4;
        const float* yg1 = y + (size_t)sPerm[96 + rb] * DF + q * 4;
        uint32_t aSts1 = su + OFF_A1 + (uint32_t)rb * ASTRIDE + (uint32_t)q * 8;
        __syncthreads();   // A0 ready

        float acc[4][4][4];
#pragma unroll
        for (int mt = 0; mt < 4; mt++)
#pragma unroll
            for (int j = 0; j < 4; j++)
#pragma unroll
                for (int c = 0; c < 4; c++) acc[mt][j][c] = 0.0f;

        // ============ GEMM1(s0) + pipelined gather of A1 ==========================
        gemm256<true>(su + OFF_A0, Wf1, acc, lane, w, yg0, yg1, aSts1);
        __syncthreads();   // A0 fully read; A1 gather STS all done

        // ---- H0 = tanh(acc + b1) -> A0 -------------------------------------------
#pragma unroll
        for (int mt = 0; mt < 4; mt++)
#pragma unroll
            for (int sub = 0; sub < 2; sub++) {
                int m = mt * 16 + sub * 8 + (lane >> 2);
#pragma unroll
                for (int j = 0; j < 4; j++) {
                    int n = w * 32 + j * 8 + (lane & 3) * 2;
                    float h0 = tanh_approx(acc[mt][j][sub * 2 + 0] + sB1[n]);
                    float h1 = tanh_approx(acc[mt][j][sub * 2 + 1] + sB1[n + 1]);
                    *(__half2*)(smem + OFF_A0 + (uint32_t)m * ASTRIDE + n * 2) =
                        __floats2half2_rn(h0, h1);
                }
            }
        __syncthreads();   // H0 ready

#pragma unroll
        for (int mt = 0; mt < 4; mt++)
#pragma unroll
            for (int j = 0; j < 4; j++)
#pragma unroll
                for (int c = 0; c < 4; c++) acc[mt][j][c] = 0.0f;

        // ============ GEMM2(s0) =====================================================
        gemm256<false>(su + OFF_A0, Wf2, acc, lane, w, yg0, yg1, 0);

        // ---- epilogue s0 ----------------------------------------------------------
#pragma unroll
        for (int mt = 0; mt < 4; mt++)
#pragma unroll
            for (int sub = 0; sub < 2; sub++) {
                int m = mt * 16 + sub * 8 + (lane >> 2);
                if (m < rows0) {
                    int row = sPerm[m];
#pragma unroll
                    for (int j = 0; j < 4; j++) {
                        int n = w * 32 + j * 8 + (lane & 3) * 2;
                        float2 o;
                        o.x = sC1[n]     * (acc[mt][j][sub * 2 + 0] + sB2[n]);
                        o.y = sC1[n + 1] * (acc[mt][j][sub * 2 + 1] + sB2[n + 1]);
                        if (need_y) {
                            float2 yv = *(const float2*)(y + (size_t)row * DF + n);
                            o.x += cy * yv.x;
                            o.y += cy * yv.y;
                        }
                        *(float2*)(out + (size_t)row * DF + n) = o;
                    }
                }
            }

        // ============ subtile 1 (A1 already gathered) ===============================
        if (rows1 > 0) {
#pragma unroll
            for (int mt = 0; mt < 4; mt++)
#pragma unroll
                for (int j = 0; j < 4; j++)
#pragma unroll
                    for (int c = 0; c < 4; c++) acc[mt][j][c] = 0.0f;

            gemm256<false>(su + OFF_A1, Wf1, acc, lane, w, yg0, yg1, 0);
            __syncthreads();   // A1 fully read before H1 overwrite

#pragma unroll
            for (int mt = 0; mt < 4; mt++)
#pragma unroll
                for (int sub = 0; sub < 2; sub++) {
                    int m = mt * 16 + sub * 8 + (lane >> 2);
#pragma unroll
                    for (int j = 0; j < 4; j++) {
                        int n = w * 32 + j * 8 + (lane & 3) * 2;
                        float h0 = tanh_approx(acc[mt][j][sub * 2 + 0] + sB1[n]);
                        float h1 = tanh_approx(acc[mt][j][sub * 2 + 1] + sB1[n + 1]);
                        *(__half2*)(smem + OFF_A1 + (uint32_t)m * ASTRIDE + n * 2) =
                            __floats2half2_rn(h0, h1);
                    }
                }
            __syncthreads();   // H1 ready

#pragma unroll
            for (int mt = 0; mt < 4; mt++)
#pragma unroll
                for (int j = 0; j < 4; j++)
#pragma unroll
                    for (int c = 0; c < 4; c++) acc[mt][j][c] = 0.0f;

            gemm256<false>(su + OFF_A1, Wf2, acc, lane, w, yg0, yg1, 0);

#pragma unroll
            for (int mt = 0; mt < 4; mt++)
#pragma unroll
                for (int sub = 0; sub < 2; sub++) {
                    int m = mt * 16 + sub * 8 + (lane >> 2);
                    if (m < rows1) {
                        int row = sPerm[64 + m];
#pragma unroll
                        for (int j = 0; j < 4; j++) {
                            int n = w * 32 + j * 8 + (lane & 3) * 2;
                            float2 o;
                            o.x = sC1[n]     * (acc[mt][j][sub * 2 + 0] + sB2[n]);
                            o.y = sC1[n + 1] * (acc[mt][j][sub * 2 + 1] + sB2[n + 1]);
                            if (need_y) {
                                float2 yv = *(const float2*)(y + (size_t)row * DF + n);
                                o.x += cy * yv.x;
                                o.y += cy * yv.y;
                            }
                            *(float2*)(out + (size_t)row * DF + n) = o;
                        }
                    }
                }
        }
    }

    // ---- self-reset routing state for next graph replay ----------------------
    __syncthreads();
    if (tid == 0) {
        int old = atomicAdd(&g_done, 1);
        if (old == nGrid - 1) {
            for (int q = 0; q < NE; q++) g_cursor[q] = 0;
            g_done = 0;
            __threadfence();
        }
    }
}

// ---------------- launcher ------------------------------------------------------
extern "C" void kernel_launch(void* const* d_in, const int* in_sizes, int n_in,
                              void* d_out, int out_size)
{
    const float* t      = (const float*)d_in[0];
    const float* y      = (const float*)d_in[1];
    const float* W1     = (const float*)d_in[2];
    const float* b1     = (const float*)d_in[3];
    const float* W2     = (const float*)d_in[4];
    const float* b2     = (const float*)d_in[5];
    const float* scales = (const float*)d_in[6];
    const float* sha    = (const float*)d_in[7];
    const float* shb    = (const float*)d_in[8];
    float* out = (float*)d_out;
    int B = in_sizes[0];

    int nb = (B + 255) / 256;
    k_prep<<<512 + nb, 256>>>(W1, W2, t, B);

    cudaFuncSetAttribute(k_moe, cudaFuncAttributeMaxDynamicSharedMemorySize, SMEM_BYTES);
    int grid = (B + 2 * TM - 1) / (2 * TM) + NE;
    k_moe<<<grid, NT, SMEM_BYTES>>>(y, b1, b2, scales, sha, shb, out, grid);
}

// round 16
// speedup vs baseline: 1.0519x; 1.0519x over previous
#include <cuda_runtime.h>
#include <cuda_fp16.h>
#include <stdint.h>
#include <math.h>

#define DF 256
#define NE 8
#define TM 64
#define NT 256
#define MAXB 32768

// ---- smem layout (bytes) ----
#define OFF_PERM 0
#define OFF_B1   1024
#define OFF_B2   2048
#define OFF_C1   3072
#define OFF_A0   4096
#define ASTRIDE  528                        // 256 halfs + pad (conflict-free LDSM)
#define ABUF     (64*ASTRIDE)               // 33792
#define OFF_A1   (OFF_A0 + ABUF)
#define SMEM_BYTES (OFF_A1 + ABUF)          // 71680 -> 2 CTAs/SM

// ---------------- device scratch (zero-initialized at load) --------------------
// g_cursor starts zero (static init); reset ONLY by k_moe's tail after each run.
__device__ int g_cursor[NE];
__device__ int g_done;
__device__ int g_perm[NE * MAXB];
// weights in mma-B fragment layout: [mat][e][kc][wid][j][lane] -> uint4
__device__ __align__(16) uint4 g_wf[2][NE * 8 * 8 * 4 * 32];

__device__ __forceinline__ int expert_of(float t) {
    int e = (int)(t * 8.0f);
    if (e > NE - 1) e = NE - 1;
    if (e < 0) e = 0;
    return e;
}

// ---- merged prep: blocks [0,512) build fragment weights; rest scatter ----------
__global__ void k_prep(const float* __restrict__ W1, const float* __restrict__ W2,
                       const float* __restrict__ t, int B) {
    if (blockIdx.x < 512) {
        int i = blockIdx.x * 256 + threadIdx.x;   // 0..131071
        int mat = i >> 16;
        int u   = i & 65535;
        int tt = u & 31, j = (u >> 5) & 3, wd = (u >> 7) & 7;
        int kc = (u >> 10) & 7, e = u >> 13;
        int n  = wd * 32 + j * 8 + (tt >> 2);
        int k0 = kc * 32 + (tt & 3) * 2;
        const float* W = (mat ? W2 : W1) + (size_t)e * DF * DF + (size_t)n * DF + k0;
        uint4 o;
        __half2 h;
        h = __floats2half2_rn(W[0],  W[1]);  o.x = *(uint32_t*)&h;
        h = __floats2half2_rn(W[8],  W[9]);  o.y = *(uint32_t*)&h;
        h = __floats2half2_rn(W[16], W[17]); o.z = *(uint32_t*)&h;
        h = __floats2half2_rn(W[24], W[25]); o.w = *(uint32_t*)&h;
        g_wf[mat][u] = o;
    } else {
        __shared__ int h[NE], bb[NE];
        if (threadIdx.x < NE) h[threadIdx.x] = 0;
        __syncthreads();
        int i = (blockIdx.x - 512) * blockDim.x + threadIdx.x;
        int e = 0, r = 0;
        bool valid = (i < B);
        if (valid) { e = expert_of(t[i]); r = atomicAdd(&h[e], 1); }
        __syncthreads();
        if (threadIdx.x < NE && h[threadIdx.x])
            bb[threadIdx.x] = atomicAdd(&g_cursor[threadIdx.x], h[threadIdx.x]);
        __syncthreads();
        if (valid) g_perm[e * MAXB + bb[e] + r] = i;
    }
}

// ---------------- helpers ----------------------------------------------------------
__device__ __forceinline__ float sigmf(float x) { return 1.0f / (1.0f + expf(-x)); }
__device__ __forceinline__ float tanh_approx(float x) {
    float r;
    asm("tanh.approx.f32 %0, %1;" : "=f"(r) : "f"(x));
    return r;
}

__device__ __forceinline__ void ldsm4(uint32_t* r, uint32_t addr) {
    asm volatile("ldmatrix.sync.aligned.m8n8.x4.shared.b16 {%0,%1,%2,%3}, [%4];"
        : "=r"(r[0]), "=r"(r[1]), "=r"(r[2]), "=r"(r[3]) : "r"(addr));
}
__device__ __forceinline__ void mma_f16(float* d, const uint32_t* a, uint32_t b0, uint32_t b1) {
    asm volatile("mma.sync.aligned.m16n8k16.row.col.f32.f16.f16.f32 "
        "{%0,%1,%2,%3}, {%4,%5,%6,%7}, {%8,%9}, {%0,%1,%2,%3};"
        : "+f"(d[0]), "+f"(d[1]), "+f"(d[2]), "+f"(d[3])
        : "r"(a[0]), "r"(a[1]), "r"(a[2]), "r"(a[3]), "r"(b0), "r"(b1));
}

__device__ __forceinline__ void sts_f16x4(uint32_t addr, float4 d) {
    __half2 p0 = __floats2half2_rn(d.x, d.y);
    __half2 p1 = __floats2half2_rn(d.z, d.w);
    uint32_t u0 = *reinterpret_cast<uint32_t*>(&p0);
    uint32_t u1 = *reinterpret_cast<uint32_t*>(&p1);
    asm volatile("st.shared.v2.b32 [%0], {%1,%2};" :: "r"(addr), "r"(u0), "r"(u1) : "memory");
}

// GEMM: warp tile 64(M) x 32(N). Inner loop split into a ks0 sweep and a ks1
// sweep over all 16 accumulators -> dependent MMAs to the same acc are 16
// instructions apart (beyond HMMA RAW latency). B prefetch folded into ks1.
template<bool GATHER>
__device__ __forceinline__ void gemm256(uint32_t aBuf, const uint4* __restrict__ Wf,
                                        float (&acc)[4][4][4], int lane, int w,
                                        const float* yg0, const float* yg1, uint32_t aSts1) {
    uint32_t aBase = aBuf
        + (uint32_t)(((lane >> 3) & 1) * 8 + (lane & 7)) * ASTRIDE
        + (uint32_t)(lane >> 4) * 16;
    const int rot = w;

    uint4 Bv[4];
#pragma unroll
    for (int j = 0; j < 4; j++) Bv[j] = Wf[rot * 1024 + j * 32];   // chunk `rot`

#pragma unroll
    for (int kc = 0; kc < 8; kc++) {
        int kk  = (kc + rot) & 7;
        int kkn = (kk + 1) & 7;
        float4 v0, v1;
        if (GATHER) {
            v0 = *(const float4*)(yg0 + kc * 32);
            v1 = *(const float4*)(yg1 + kc * 32);
        }
        uint32_t aAddr = aBase + (uint32_t)kk * 64;
        uint32_t a[32];
#pragma unroll
        for (int mt = 0; mt < 4; mt++) {
            ldsm4(a + mt * 8,     aAddr + (uint32_t)(mt * 16) * ASTRIDE);        // ks0
            ldsm4(a + mt * 8 + 4, aAddr + (uint32_t)(mt * 16) * ASTRIDE + 32);   // ks1
        }
        // ---- ks0 sweep: 16 independent MMAs ---------------------------------
#pragma unroll
        for (int j = 0; j < 4; j++)
#pragma unroll
            for (int mt = 0; mt < 4; mt++)
                mma_f16(acc[mt][j], a + mt * 8, Bv[j].x, Bv[j].y);
        // ---- ks1 sweep (+ B prefetch for next chunk) ------------------------
#pragma unroll
        for (int j = 0; j < 4; j++) {
            uint32_t bz = Bv[j].z, bw = Bv[j].w;
            if (kc < 7) Bv[j] = Wf[kkn * 1024 + j * 32];
#pragma unroll
            for (int mt = 0; mt < 4; mt++)
                mma_f16(acc[mt][j], a + mt * 8 + 4, bz, bw);
        }
        if (GATHER) {
            sts_f16x4(aSts1 + (uint32_t)kc * 64, v0);
            sts_f16x4(aSts1 + 32 * ASTRIDE + (uint32_t)kc * 64, v1);
        }
    }
}

// ---------------- main fused MoE kernel --------------------------------------------
__global__ __launch_bounds__(NT, 2) void k_moe(
    const float* __restrict__ y,
    const float* __restrict__ b1, const float* __restrict__ b2,
    const float* __restrict__ scales,
    const float* __restrict__ shifta, const float* __restrict__ shiftb,
    float* __restrict__ out, int nGrid)
{
    extern __shared__ char smem[];
    const int tid  = threadIdx.x;
    const int lane = tid & 31;
    const int w    = tid >> 5;    // 8 warps along N (32 cols each)

    // ---- block -> (expert, tile-pair) -----------------------------------------
    int bid = blockIdx.x, e = 0, local = -1, acc_t = 0, cnt_e = 0;
#pragma unroll
    for (int q = 0; q < NE; q++) {
        int c  = g_cursor[q];
        int nt = (c + TM - 1) / TM;
        int np = (nt + 1) >> 1;
        if (local < 0 && bid < acc_t + np) { e = q; local = bid - acc_t; cnt_e = c; }
        acc_t += np;
    }

    if (local >= 0) {
        uint32_t su;
        asm("{ .reg .u64 t; cvta.to.shared.u64 t, %1; cvt.u32.u64 %0, t; }" : "=r"(su) : "l"(smem));

        int*   sPerm = (int*)(smem + OFF_PERM);   // 128 rows (both subtiles)
        float* sB1   = (float*)(smem + OFF_B1);
        float* sB2   = (float*)(smem + OFF_B2);
        float* sC1   = (float*)(smem + OFF_C1);

        int base0 = local * 2 * TM;
        int rows0 = cnt_e - base0;          if (rows0 > TM) rows0 = TM;
        int rows1 = cnt_e - base0 - TM;     if (rows1 > TM) rows1 = TM;

        float sa = sigmf(shifta[0]);
        float sb = sigmf(shiftb[0]);
        float cy = 0.5f * (sb - sa);
        sB1[tid] = b1[e * DF + tid];
        sB2[tid] = b2[e * DF + tid];
        sC1[tid] = 0.5f * (sb + sa) * sigmf(scales[tid]);
        {
            int gi = base0 + tid;
            if (gi > cnt_e - 1) gi = cnt_e - 1;
            if (tid < 128) sPerm[tid] = g_perm[e * MAXB + gi];
        }
        __syncthreads();

        const uint4* Wf1 = g_wf[0] + e * 8192 + w * 128 + lane;
        const uint4* Wf2 = g_wf[1] + e * 8192 + w * 128 + lane;
        bool need_y = (cy != 0.0f);

        int rb = tid >> 3, q = tid & 7;
        // ---- gather A0 (subtile 0) ---------------------------------------------
        {
            const float* y0 = y + (size_t)sPerm[rb] * DF + q * 4;
            const float* y1 = y + (size_t)sPerm[rb + 32] * DF + q * 4;
            uint32_t d0 = su + OFF_A0 + (uint32_t)rb * ASTRIDE + (uint32_t)q * 8;
            uint32_t d1 = d0 + 32 * ASTRIDE;
#pragma unroll
            for (int c = 0; c < 8; c++) {
                float4 v0 = *(const float4*)(y0 + c * 32);
                float4 v1 = *(const float4*)(y1 + c * 32);
                sts_f16x4(d0 + c * 64, v0);
                sts_f16x4(d1 + c * 64, v1);
            }
        }
        const float* yg0 = y + (size_t)sPerm[64 + rb] * DF + q * 4;
        const float* yg1 = y + (size_t)sPerm[96 + rb] * DF + q * 4;
        uint32_t aSts1 = su + OFF_A1 + (uint32_t)rb * ASTRIDE + (uint32_t)q * 8;
        __syncthreads();   // A0 ready

        float acc[4][4][4];
#pragma unroll
        for (int mt = 0; mt < 4; mt++)
#pragma unroll
            for (int j = 0; j < 4; j++)
#pragma unroll
                for (int c = 0; c < 4; c++) acc[mt][j][c] = 0.0f;

        // ============ GEMM1(s0) + pipelined gather of A1 ==========================
        gemm256<true>(su + OFF_A0, Wf1, acc, lane, w, yg0, yg1, aSts1);
        __syncthreads();   // A0 fully read; A1 gather STS done

        // ---- H0 = tanh(acc + b1) -> A0 -------------------------------------------
#pragma unroll
        for (int mt = 0; mt < 4; mt++)
#pragma unroll
            for (int sub = 0; sub < 2; sub++) {
                int m = mt * 16 + sub * 8 + (lane >> 2);
#pragma unroll
                for (int j = 0; j < 4; j++) {
                    int n = w * 32 + j * 8 + (lane & 3) * 2;
                    float h0 = tanh_approx(acc[mt][j][sub * 2 + 0] + sB1[n]);
                    float h1 = tanh_approx(acc[mt][j][sub * 2 + 1] + sB1[n + 1]);
                    *(__half2*)(smem + OFF_A0 + (uint32_t)m * ASTRIDE + n * 2) =
                        __floats2half2_rn(h0, h1);
                }
            }
        __syncthreads();   // H0 ready

#pragma unroll
        for (int mt = 0; mt < 4; mt++)
#pragma unroll
            for (int j = 0; j < 4; j++)
#pragma unroll
                for (int c = 0; c < 4; c++) acc[mt][j][c] = 0.0f;

        // ============ GEMM2(s0) =====================================================
        gemm256<false>(su + OFF_A0, Wf2, acc, lane, w, yg0, yg1, 0);

        // ---- epilogue s0 ----------------------------------------------------------
#pragma unroll
        for (int mt = 0; mt < 4; mt++)
#pragma unroll
            for (int sub = 0; sub < 2; sub++) {
                int m = mt * 16 + sub * 8 + (lane >> 2);
                if (m < rows0) {
                    int row = sPerm[m];
#pragma unroll
                    for (int j = 0; j < 4; j++) {
                        int n = w * 32 + j * 8 + (lane & 3) * 2;
                        float2 o;
                        o.x = sC1[n]     * (acc[mt][j][sub * 2 + 0] + sB2[n]);
                        o.y = sC1[n + 1] * (acc[mt][j][sub * 2 + 1] + sB2[n + 1]);
                        if (need_y) {
                            float2 yv = *(const float2*)(y + (size_t)row * DF + n);
                            o.x += cy * yv.x;
                            o.y += cy * yv.y;
                        }
                        *(float2*)(out + (size_t)row * DF + n) = o;
                    }
                }
            }

        // ============ subtile 1 (A1 already gathered) ===============================
        if (rows1 > 0) {
#pragma unroll
            for (int mt = 0; mt < 4; mt++)
#pragma unroll
                for (int j = 0; j < 4; j++)
#pragma unroll
                    for (int c = 0; c < 4; c++) acc[mt][j][c] = 0.0f;

            gemm256<false>(su + OFF_A1, Wf1, acc, lane, w, yg0, yg1, 0);
            __syncthreads();   // A1 fully read before H1 overwrite

#pragma unroll
            for (int mt = 0; mt < 4; mt++)
#pragma unroll
                for (int sub = 0; sub < 2; sub++) {
                    int m = mt * 16 + sub * 8 + (lane >> 2);
#pragma unroll
                    for (int j = 0; j < 4; j++) {
                        int n = w * 32 + j * 8 + (lane & 3) * 2;
                        float h0 = tanh_approx(acc[mt][j][sub * 2 + 0] + sB1[n]);
                        float h1 = tanh_approx(acc[mt][j][sub * 2 + 1] + sB1[n + 1]);
                        *(__half2*)(smem + OFF_A1 + (uint32_t)m * ASTRIDE + n * 2) =
                            __floats2half2_rn(h0, h1);
                    }
                }
            __syncthreads();   // H1 ready

#pragma unroll
            for (int mt = 0; mt < 4; mt++)
#pragma unroll
                for (int j = 0; j < 4; j++)
#pragma unroll
                    for (int c = 0; c < 4; c++) acc[mt][j][c] = 0.0f;

            gemm256<false>(su + OFF_A1, Wf2, acc, lane, w, yg0, yg1, 0);

#pragma unroll
            for (int mt = 0; mt < 4; mt++)
#pragma unroll
                for (int sub = 0; sub < 2; sub++) {
                    int m = mt * 16 + sub * 8 + (lane >> 2);
                    if (m < rows1) {
                        int row = sPerm[64 + m];
#pragma unroll
                        for (int j = 0; j < 4; j++) {
                            int n = w * 32 + j * 8 + (lane & 3) * 2;
                            float2 o;
                            o.x = sC1[n]     * (acc[mt][j][sub * 2 + 0] + sB2[n]);
                            o.y = sC1[n + 1] * (acc[mt][j][sub * 2 + 1] + sB2[n + 1]);
                            if (need_y) {
                                float2 yv = *(const float2*)(y + (size_t)row * DF + n);
                                o.x += cy * yv.x;
                                o.y += cy * yv.y;
                            }
                            *(float2*)(out + (size_t)row * DF + n) = o;
                        }
                    }
                }
        }
    }

    // ---- self-reset routing state for next graph replay ----------------------
    __syncthreads();
    if (tid == 0) {
        int old = atomicAdd(&g_done, 1);
        if (old == nGrid - 1) {
            for (int q = 0; q < NE; q++) g_cursor[q] = 0;
            g_done = 0;
            __threadfence();
        }
    }
}

// ---------------- launcher ------------------------------------------------------
extern "C" void kernel_launch(void* const* d_in, const int* in_sizes, int n_in,
                              void* d_out, int out_size)
{
    const float* t      = (const float*)d_in[0];
    const float* y      = (const float*)d_in[1];
    const float* W1     = (const float*)d_in[2];
    const float* b1     = (const float*)d_in[3];
    const float* W2     = (const float*)d_in[4];
    const float* b2     = (const float*)d_in[5];
    const float* scales = (const float*)d_in[6];
    const float* sha    = (const float*)d_in[7];
    const float* shb    = (const float*)d_in[8];
    float* out = (float*)d_out;
    int B = in_sizes[0];

    int nb = (B + 255) / 256;
    k_prep<<<512 + nb, 256>>>(W1, W2, t, B);

    cudaFuncSetAttribute(k_moe, cudaFuncAttributeMaxDynamicSharedMemorySize, SMEM_BYTES);
    int grid = (B + 2 * TM - 1) / (2 * TM) + NE;
    k_moe<<<grid, NT, SMEM_BYTES>>>(y, b1, b2, scales, sha, shb, out, grid);
}